// round 11
// baseline (speedup 1.0000x reference)
#include <cuda_runtime.h>
#include <cstddef>

#define VOCABP 50001
#define EMB    200
#define HID    128
#define BATCH  256
#define TSTEPS 500
#define NC     6
#define DENSE  64
#define NGATE  512   // 4*HID
#define HOFF   203   // row offset of h-part inside W [331, 512]

#define SCAN_T    512                 // thread = (row = tid&3, u = tid>>2); owns all 4 gates
#define SMEM_COLS 416                 // gate columns with fp32 weights in SMEM
#define TAILC     96                  // o-gate columns c in [416,512) (u >= 32), L2-streamed
#define WPITCH    132                 // pitch (528B): banks 4c+k -> conflict-free weight/h reads
// Ws(416*132) + h double buffer(2*4*132) floats = 223,872 B <= 232,448 opt-in cap
#define SCAN_SMEM_BYTES ((SMEM_COLS*WPITCH + 2*4*WPITCH) * 4)

// ---------------- scratch (no allocations allowed) ----------------
__device__ float g_tab[2ull * VOCABP * NGATE];   // projected vocab tables, ~205 MB
__device__ float g_captab[2 * 4 * NGATE];        // cap one-hot projection + bias
__device__ float g_wtail[2 * 32 * TAILC * 4];    // tail W_h: [d][kchunk][ct][4k] (16B units)
__device__ float g_hfinal[2 * BATCH * HID];      // final hidden states per direction

__device__ __forceinline__ float sigf(float x) { return 1.0f / (1.0f + __expf(-x)); }
__device__ __forceinline__ float tanh_fast(float x) {
    return 1.0f - 2.0f / (__expf(2.0f * x) + 1.0f);
}

// packed fp32x2 FMA: d.lo += a.lo*b.lo ; d.hi += a.hi*b.hi   (exact fp32 per lane)
__device__ __forceinline__ void ffma2(unsigned long long& d,
                                      unsigned long long a, unsigned long long b) {
    asm("fma.rn.f32x2 %0, %1, %2, %0;" : "+l"(d) : "l"(a), "l"(b));
}
__device__ __forceinline__ float2 ull2f2(unsigned long long v) {
    float2 r; asm("mov.b64 {%0,%1}, %2;" : "=f"(r.x), "=f"(r.y) : "l"(v)); return r;
}
__device__ __forceinline__ unsigned long long fdup(float w) {
    unsigned long long r; asm("mov.b64 %0, {%1,%1};" : "=l"(r) : "f"(w)); return r;
}
__device__ __forceinline__ unsigned long long f2_to_ull(float x, float y) {
    unsigned long long r; asm("mov.b64 %0, {%1,%2};" : "=l"(r) : "f"(x), "f"(y)); return r;
}

// ---------------- kernel 1: Tab[d] = word_emb @ W_d[0:200,:] ----------------
__global__ void __launch_bounds__(512) tab_kernel(const float* __restrict__ emb,
                                                  const float* __restrict__ Wfw,
                                                  const float* __restrict__ Wbw)
{
    __shared__ float es[EMB * 16];   // [k][r] transposed tile, 12.8 KB
    const int d  = blockIdx.y;
    const int v0 = blockIdx.x * 16;
    const float* __restrict__ W = d ? Wbw : Wfw;
    const int tid = threadIdx.x;

    for (int i = tid; i < 16 * EMB; i += 512) {
        int r = i / EMB, k = i % EMB;
        int v = v0 + r;
        es[k * 16 + r] = (v < VOCABP) ? emb[(size_t)v * EMB + k] : 0.0f;
    }
    __syncthreads();

    const int c = tid;   // gate column 0..511
    unsigned long long acc[8];  // 8 packed pairs = 16 rows
#pragma unroll
    for (int p = 0; p < 8; p++) acc[p] = 0ull;

#pragma unroll 4
    for (int k = 0; k < EMB; k++) {
        unsigned long long wd = fdup(__ldg(&W[k * NGATE + c]));
        const ulonglong2* e2 = (const ulonglong2*)&es[k * 16];
        ulonglong2 ea = e2[0], eb = e2[1], ec = e2[2], ed = e2[3];
        ffma2(acc[0], ea.x, wd); ffma2(acc[1], ea.y, wd);
        ffma2(acc[2], eb.x, wd); ffma2(acc[3], eb.y, wd);
        ffma2(acc[4], ec.x, wd); ffma2(acc[5], ec.y, wd);
        ffma2(acc[6], ed.x, wd); ffma2(acc[7], ed.y, wd);
    }

    float* out = &g_tab[((size_t)d * VOCABP + v0) * NGATE + c];
#pragma unroll
    for (int p = 0; p < 8; p++) {
        float2 f = ull2f2(acc[p]);
        if (v0 + 2 * p     < VOCABP) out[(size_t)(2 * p)     * NGATE] = f.x;
        if (v0 + 2 * p + 1 < VOCABP) out[(size_t)(2 * p + 1) * NGATE] = f.y;
    }
}

// ---------------- kernel 2a: cap table (+ bias folded in) ----------------
__global__ void captab_kernel(const float* __restrict__ cemb,
                              const float* __restrict__ Wfw, const float* __restrict__ bfw,
                              const float* __restrict__ Wbw, const float* __restrict__ bbw)
{
    int idx = blockIdx.x * blockDim.x + threadIdx.x;
    if (idx >= 2 * 4 * NGATE) return;
    int d  = idx / (4 * NGATE);
    int ci = (idx / NGATE) & 3;
    int c  = idx % NGATE;
    const float* W = d ? Wbw : Wfw;
    const float* b = d ? bbw : bfw;
    float v = b[c];
#pragma unroll
    for (int j = 0; j < 3; j++) v += cemb[ci * 3 + j] * W[(EMB + j) * NGATE + c];
    g_captab[idx] = v;
}

// ---------------- kernel 2b: tail W_h (cols 416..511), chunk-interleaved ----------------
// g_wtail[((d*32 + k/4)*TAILC + ct)*4 + (k&3)] = W[(HOFF+k)*NGATE + 416 + ct]
__global__ void wtail_kernel(const float* __restrict__ Wfw, const float* __restrict__ Wbw)
{
    int idx = blockIdx.x * blockDim.x + threadIdx.x;
    if (idx >= 2 * HID * TAILC) return;
    int d   = idx / (HID * TAILC);
    int rem = idx % (HID * TAILC);
    int k   = rem / TAILC;
    int ct  = rem % TAILC;
    const float* W = d ? Wbw : Wfw;
    g_wtail[((d * 32 + (k >> 2)) * TAILC + ct) * 4 + (k & 3)] =
        W[(HOFF + k) * NGATE + SMEM_COLS + ct];
}

// ---------------- kernel 3: the recurrent scan (gate-owner mapping) ----------------
// grid = 128 CTAs: blockIdx.x>>6 = direction, (blockIdx.x&63)*4 = first batch row.
// 512 threads: thread (row = tid&3, u = tid>>2) computes gate columns
// {u, u+128, u+256, u+384} of batch row (b0+row) over full k, and performs its own
// gate update. No staging; double-buffered h; ONE barrier per step.
__global__ void __launch_bounds__(SCAN_T, 1) scan_kernel(const int* __restrict__ words,
                                                         const int* __restrict__ caps,
                                                         const float* __restrict__ Wfw,
                                                         const float* __restrict__ Wbw)
{
    extern __shared__ float sm[];
    float* Ws = sm;                        // [SMEM_COLS][WPITCH] transposed weights
    float* hb = Ws + SMEM_COLS * WPITCH;   // [2 buffers][4 rows][WPITCH]

    const int tid = threadIdx.x;
    const int d   = blockIdx.x >> 6;
    const int b0  = (blockIdx.x & 63) * 4;
    const float* __restrict__ W = d ? Wbw : Wfw;

    // stage W_h columns [0, SMEM_COLS) transposed: Ws[c][k]  (one-time cost)
    for (int i = tid; i < HID * SMEM_COLS; i += SCAN_T) {
        int k = i / SMEM_COLS, c = i % SMEM_COLS;   // coalesced global read
        Ws[c * WPITCH + k] = W[(HOFF + k) * NGATE + c];
    }
    for (int i = tid; i < 2 * 4 * WPITCH; i += SCAN_T) hb[i] = 0.0f;

    const int row = tid & 3;
    const int u   = tid >> 2;                 // 0..127; warp w holds u in [8w, 8w+8)
    const bool is_tail = (u >= 32);           // warp-uniform: warps 4..15
    const float* __restrict__ tabd = &g_tab[(size_t)d * VOCABP * NGATE];
    const float* __restrict__ capd = &g_captab[d * 4 * NGATE];
    const float* __restrict__ wi  = &Ws[(u)       * WPITCH];
    const float* __restrict__ wj  = &Ws[(u + 128) * WPITCH];
    const float* __restrict__ wf_ = &Ws[(u + 256) * WPITCH];
    const float* __restrict__ wo  = &Ws[(is_tail ? 0 : (u + 384)) * WPITCH]; // dummy for tail
    const ulonglong2* __restrict__ wt =
        (const ulonglong2*)g_wtail + (size_t)d * 32 * TAILC + (is_tail ? (u - 32) : 0);

    // cap contributions for all 3 cap indices x 4 gates (12 regs)
    const float ci0 = __ldg(&capd[0 * NGATE + u]),       ci1 = __ldg(&capd[1 * NGATE + u]),       ci2 = __ldg(&capd[2 * NGATE + u]);
    const float cj0 = __ldg(&capd[0 * NGATE + u + 128]), cj1 = __ldg(&capd[1 * NGATE + u + 128]), cj2 = __ldg(&capd[2 * NGATE + u + 128]);
    const float cf0 = __ldg(&capd[0 * NGATE + u + 256]), cf1 = __ldg(&capd[1 * NGATE + u + 256]), cf2 = __ldg(&capd[2 * NGATE + u + 256]);
    const float co0 = __ldg(&capd[0 * NGATE + u + 384]), co1 = __ldg(&capd[1 * NGATE + u + 384]), co2 = __ldg(&capd[2 * NGATE + u + 384]);

    const int* __restrict__ wrow = &words[(b0 + row) * TSTEPS];
    const int* __restrict__ crow = &caps [(b0 + row) * TSTEPS];

    float cst = 0.0f, hh = 0.0f;

    __syncthreads();

    // prologue: step-0 x-gate values
    float xgi, xgj, xgf, xgo;
    {
        int t0 = d ? (TSTEPS - 1) : 0;
        int wv = __ldg(&wrow[t0]);
        int cv = __ldg(&crow[t0]);
        const float* tr = &tabd[(size_t)wv * NGATE];
        xgi = __ldg(&tr[u])       + ((cv == 0) ? ci0 : ((cv == 1) ? ci1 : ci2));
        xgj = __ldg(&tr[u + 128]) + ((cv == 0) ? cj0 : ((cv == 1) ? cj1 : cj2));
        xgf = __ldg(&tr[u + 256]) + ((cv == 0) ? cf0 : ((cv == 1) ? cf1 : cf2));
        xgo = __ldg(&tr[u + 384]) + ((cv == 0) ? co0 : ((cv == 1) ? co1 : co2));
    }

    for (int t = 0; t < TSTEPS; t++) {
        // issue next-step index loads early (L1-hot)
        int tt = d ? (TSTEPS - 2 - t) : (t + 1);
        if (t + 1 >= TSTEPS) tt = 0;                // clamp; values unused
        int nw = __ldg(&wrow[tt]);
        int nc = __ldg(&crow[tt]);

        const float* h = hb + (t & 1) * 4 * WPITCH + row * WPITCH;
        float*      hn = hb + ((t + 1) & 1) * 4 * WPITCH;

        // 4 gate dot-products over k (f32x2 k-pairs)
        unsigned long long Ai = 0ull, Aj = 0ull, Af = 0ull, Ao = 0ull;
        if (!is_tail) {
#pragma unroll 4
            for (int kk = 0; kk < HID; kk += 4) {
                ulonglong2 hp = *(const ulonglong2*)&h[kk];        // 4 rows x 16B, 1 wf
                ulonglong2 pi = *(const ulonglong2*)&wi[kk];       // 8 cols x bcast, 1 wf
                ulonglong2 pj = *(const ulonglong2*)&wj[kk];
                ulonglong2 pf = *(const ulonglong2*)&wf_[kk];
                ulonglong2 po = *(const ulonglong2*)&wo[kk];
                ffma2(Ai, hp.x, pi.x); ffma2(Ai, hp.y, pi.y);
                ffma2(Aj, hp.x, pj.x); ffma2(Aj, hp.y, pj.y);
                ffma2(Af, hp.x, pf.x); ffma2(Af, hp.y, pf.y);
                ffma2(Ao, hp.x, po.x); ffma2(Ao, hp.y, po.y);
            }
        } else {
            // o-gate column from L2 (chunk-interleaved, contiguous per warp, 48KB/dir)
#pragma unroll 4
            for (int kk = 0; kk < HID; kk += 4) {
                ulonglong2 hp = *(const ulonglong2*)&h[kk];
                ulonglong2 pi = *(const ulonglong2*)&wi[kk];
                ulonglong2 pj = *(const ulonglong2*)&wj[kk];
                ulonglong2 pf = *(const ulonglong2*)&wf_[kk];
                ulonglong2 po = __ldg(&wt[(size_t)(kk >> 2) * TAILC]);
                ffma2(Ai, hp.x, pi.x); ffma2(Ai, hp.y, pi.y);
                ffma2(Aj, hp.x, pj.x); ffma2(Aj, hp.y, pj.y);
                ffma2(Af, hp.x, pf.x); ffma2(Af, hp.y, pf.y);
                ffma2(Ao, hp.x, po.x); ffma2(Ao, hp.y, po.y);
            }
        }

        // local gate update (no staging, no extra barrier)
        {
            float2 f;
            f = ull2f2(Ai); float gi = f.x + f.y + xgi;
            f = ull2f2(Aj); float gj = f.x + f.y + xgj;
            f = ull2f2(Af); float gf = f.x + f.y + xgf;
            f = ull2f2(Ao); float go = f.x + f.y + xgo;
            cst = sigf(gf + 1.0f) * cst + sigf(gi) * tanh_fast(gj);
            hh  = sigf(go) * tanh_fast(cst);
            hn[row * WPITCH + u] = hh;
        }

        // prefetch next step's x-gates (consumed after the barrier + next k-loop)
        if (t + 1 < TSTEPS) {
            const float* tr = &tabd[(size_t)nw * NGATE];
            xgi = __ldg(&tr[u])       + ((nc == 0) ? ci0 : ((nc == 1) ? ci1 : ci2));
            xgj = __ldg(&tr[u + 128]) + ((nc == 0) ? cj0 : ((nc == 1) ? cj1 : cj2));
            xgf = __ldg(&tr[u + 256]) + ((nc == 0) ? cf0 : ((nc == 1) ? cf1 : cf2));
            xgo = __ldg(&tr[u + 384]) + ((nc == 0) ? co0 : ((nc == 1) ? co1 : co2));
        }

        __syncthreads();   // hn visible to all; WAR on h ordered (double buffer)
    }

    g_hfinal[((d * BATCH) + (b0 + row)) * HID + u] = hh;
}

// ---------------- kernel 4: dense head ----------------
__global__ void __launch_bounds__(256) dense_kernel(const float* __restrict__ W1,
                                                    const float* __restrict__ b1,
                                                    const float* __restrict__ W2,
                                                    const float* __restrict__ b2,
                                                    float* __restrict__ out)
{
    __shared__ float red[256];
    __shared__ float d1[DENSE];
    const int b = blockIdx.x, t = threadIdx.x;
    const int j = t & 63, q = t >> 6;
    const float* xin = (q < 2) ? &g_hfinal[b * HID + q * 64]
                               : &g_hfinal[(BATCH + b) * HID + (q - 2) * 64];
    const float* w   = &W1[(q * 64) * DENSE + j];
    float acc = 0.0f;
#pragma unroll 8
    for (int i = 0; i < 64; i++) acc += xin[i] * w[i * DENSE];
    red[t] = acc;
    __syncthreads();
    if (t < DENSE) {
        float a = red[t] + red[t + 64] + red[t + 128] + red[t + 192] + b1[t];
        d1[t] = (a > 0.0f) ? a : (__expf(a) - 1.0f);   // elu
    }
    __syncthreads();
    if (t < NC) {
        float a = b2[t];
#pragma unroll
        for (int k = 0; k < DENSE; k++) a += d1[k] * W2[k * NC + t];
        out[b * NC + t] = 1.0f / (1.0f + __expf(-a));  // sigmoid
    }
}

// ---------------- launch ----------------
extern "C" void kernel_launch(void* const* d_in, const int* in_sizes, int n_in,
                              void* d_out, int out_size)
{
    const int*   words = (const int*)  d_in[0];
    const int*   caps  = (const int*)  d_in[1];
    const float* emb   = (const float*)d_in[2];
    const float* cemb  = (const float*)d_in[3];
    const float* Wfw   = (const float*)d_in[4];
    const float* bfw   = (const float*)d_in[5];
    const float* Wbw   = (const float*)d_in[6];
    const float* bbw   = (const float*)d_in[7];
    const float* W1    = (const float*)d_in[8];
    const float* b1    = (const float*)d_in[9];
    const float* W2    = (const float*)d_in[10];
    const float* b2    = (const float*)d_in[11];
    float* out = (float*)d_out;

    cudaFuncSetAttribute(scan_kernel, cudaFuncAttributeMaxDynamicSharedMemorySize,
                         SCAN_SMEM_BYTES);

    wtail_kernel<<<(2 * HID * TAILC + 511) / 512, 512>>>(Wfw, Wbw);
    captab_kernel<<<8, 512>>>(cemb, Wfw, bfw, Wbw, bbw);
    tab_kernel<<<dim3((VOCABP + 15) / 16, 2), 512>>>(emb, Wfw, Wbw);
    scan_kernel<<<128, SCAN_T, SCAN_SMEM_BYTES>>>(words, caps, Wfw, Wbw);
    dense_kernel<<<BATCH, 256>>>(W1, b1, W2, b2, out);
}

// round 12
// speedup vs baseline: 1.3785x; 1.3785x over previous
#include <cuda_runtime.h>
#include <cstddef>

#define VOCABP 50001
#define EMB    200
#define HID    128
#define BATCH  256
#define TSTEPS 500
#define NC     6
#define DENSE  64
#define NGATE  512   // 4*HID
#define HOFF   203   // row offset of h-part inside W [331, 512]

#define SCAN_T    512                 // thread = (half = tid>>8, j = tid&255): cols {j, j+256}, k-half
#define SMEM_COLS 256                 // c1 columns (256..511) cached in SMEM, transposed
#define WPITCH    132                 // transposed weight pitch in floats (528B; bank stride 4)
#define GPITCH    512                 // gate staging pitch
// Ws(256*132) + h(4*128) + g(2*4*512) floats = 153,600 B (needs >48KB opt-in)
#define SCAN_SMEM_BYTES ((SMEM_COLS*WPITCH + 4*HID + 2*4*GPITCH) * 4)

// ---------------- scratch (no allocations allowed) ----------------
__device__ float g_tab[2ull * VOCABP * NGATE];    // projected vocab tables, ~205 MB
__device__ float g_captab[2 * 4 * NGATE];         // cap one-hot projection + bias
__device__ float g_hfinal[2 * BATCH * HID];       // final hidden states per direction

__device__ __forceinline__ float sigf(float x) { return 1.0f / (1.0f + __expf(-x)); }
__device__ __forceinline__ float tanh_fast(float x) {
    return 1.0f - 2.0f / (__expf(2.0f * x) + 1.0f);
}

// packed fp32x2 FMA: d.lo += a.lo*b.lo ; d.hi += a.hi*b.hi   (exact fp32 per lane)
__device__ __forceinline__ void ffma2(unsigned long long& d,
                                      unsigned long long a, unsigned long long b) {
    asm("fma.rn.f32x2 %0, %1, %2, %0;" : "+l"(d) : "l"(a), "l"(b));
}
__device__ __forceinline__ float2 ull2f2(unsigned long long v) {
    float2 r; asm("mov.b64 {%0,%1}, %2;" : "=f"(r.x), "=f"(r.y) : "l"(v)); return r;
}
__device__ __forceinline__ unsigned long long fdup(float w) {
    unsigned long long r; asm("mov.b64 %0, {%1,%1};" : "=l"(r) : "f"(w)); return r;
}
__device__ __forceinline__ unsigned long long f2_to_ull(float x, float y) {
    unsigned long long r; asm("mov.b64 %0, {%1,%2};" : "=l"(r) : "f"(x), "f"(y)); return r;
}

// ---------------- kernel 1: Tab[d] = word_emb @ W_d[0:200,:] ----------------
__global__ void __launch_bounds__(512) tab_kernel(const float* __restrict__ emb,
                                                  const float* __restrict__ Wfw,
                                                  const float* __restrict__ Wbw)
{
    __shared__ float es[EMB * 16];   // [k][r] transposed tile, 12.8 KB
    const int d  = blockIdx.y;
    const int v0 = blockIdx.x * 16;
    const float* __restrict__ W = d ? Wbw : Wfw;
    const int tid = threadIdx.x;

    for (int i = tid; i < 16 * EMB; i += 512) {
        int r = i / EMB, k = i % EMB;
        int v = v0 + r;
        es[k * 16 + r] = (v < VOCABP) ? emb[(size_t)v * EMB + k] : 0.0f;
    }
    __syncthreads();

    const int c = tid;   // gate column 0..511
    unsigned long long acc[8];  // 8 packed pairs = 16 rows
#pragma unroll
    for (int p = 0; p < 8; p++) acc[p] = 0ull;

#pragma unroll 4
    for (int k = 0; k < EMB; k++) {
        unsigned long long wd = fdup(__ldg(&W[k * NGATE + c]));
        const ulonglong2* e2 = (const ulonglong2*)&es[k * 16];
        ulonglong2 ea = e2[0], eb = e2[1], ec = e2[2], ed = e2[3];
        ffma2(acc[0], ea.x, wd); ffma2(acc[1], ea.y, wd);
        ffma2(acc[2], eb.x, wd); ffma2(acc[3], eb.y, wd);
        ffma2(acc[4], ec.x, wd); ffma2(acc[5], ec.y, wd);
        ffma2(acc[6], ed.x, wd); ffma2(acc[7], ed.y, wd);
    }

    float* out = &g_tab[((size_t)d * VOCABP + v0) * NGATE + c];
#pragma unroll
    for (int p = 0; p < 8; p++) {
        float2 f = ull2f2(acc[p]);
        if (v0 + 2 * p     < VOCABP) out[(size_t)(2 * p)     * NGATE] = f.x;
        if (v0 + 2 * p + 1 < VOCABP) out[(size_t)(2 * p + 1) * NGATE] = f.y;
    }
}

// ---------------- kernel 2: cap table (+ bias folded in) ----------------
__global__ void captab_kernel(const float* __restrict__ cemb,
                              const float* __restrict__ Wfw, const float* __restrict__ bfw,
                              const float* __restrict__ Wbw, const float* __restrict__ bbw)
{
    int idx = blockIdx.x * blockDim.x + threadIdx.x;
    if (idx >= 2 * 4 * NGATE) return;
    int d  = idx / (4 * NGATE);
    int ci = (idx / NGATE) & 3;
    int c  = idx % NGATE;
    const float* W = d ? Wbw : Wfw;
    const float* b = d ? bbw : bfw;
    float v = b[c];
#pragma unroll
    for (int j = 0; j < 3; j++) v += cemb[ci * 3 + j] * W[(EMB + j) * NGATE + c];
    g_captab[idx] = v;
}

// ---------------- kernel 3: the recurrent scan (k-split; c0 weights in registers) ----------------
// grid = 128 CTAs: blockIdx.x>>6 = direction, (blockIdx.x&63)*4 = first batch row.
// 512 threads: thread (half = tid>>8, j = tid&255) computes gate columns {j, j+256}
// for 4 batch rows over k in [half*64, half*64+64).
//   - column j   (c0): 64 k-weights held in 32 packed f32x2 REGISTERS (no smem traffic)
//   - column j+256 (c1): weights from SMEM (all 256 columns cached — no L2 tail)
// Partials staged per half; gate update: thread tid owns (row = tid>>7, unit = tid&127).
__global__ void __launch_bounds__(SCAN_T, 1) scan_kernel(const int* __restrict__ words,
                                                         const int* __restrict__ caps,
                                                         const float* __restrict__ Wfw,
                                                         const float* __restrict__ Wbw)
{
    extern __shared__ float sm[];
    float* Ws  = sm;                        // [SMEM_COLS][WPITCH] transposed c1 weights
    float* h_s = Ws + SMEM_COLS * WPITCH;   // [4][HID]
    float* g_s = h_s + 4 * HID;             // [2 halves][4][GPITCH]

    const int tid = threadIdx.x;
    const int d   = blockIdx.x >> 6;
    const int b0  = (blockIdx.x & 63) * 4;
    const float* __restrict__ W = d ? Wbw : Wfw;

    // stage c1 columns [256, 512) transposed: Ws[c-256][k]  (one-time cost)
    for (int i = tid; i < HID * SMEM_COLS; i += SCAN_T) {
        int k = i / SMEM_COLS, c = i % SMEM_COLS;   // coalesced global read
        Ws[c * WPITCH + k] = W[(HOFF + k) * NGATE + 256 + c];
    }
    h_s[tid] = 0.0f;   // 512 = 4*HID exactly

    const int half = tid >> 8;          // k-half: 0 -> [0,64), 1 -> [64,128)
    const int j    = tid & 255;
    const int c0   = j;                 // register-resident weights
    const int c1   = j + 256;           // SMEM weights
    const int k0   = half * 64;
    const float* __restrict__ tabd = &g_tab[(size_t)d * VOCABP * NGATE];
    const float* __restrict__ capd = &g_captab[d * 4 * NGATE];
    const float* __restrict__ wc1  = &Ws[j * WPITCH + k0];
    float* gh = g_s + half * 4 * GPITCH;   // this half's staging buffer

    // c0 weights: 64 fp32 -> 32 packed f32x2 registers (coalesced one-time load)
    unsigned long long wr[32];
#pragma unroll
    for (int kc = 0; kc < 16; kc++) {
        float w0 = __ldg(&W[(HOFF + k0 + 4 * kc + 0) * NGATE + c0]);
        float w1 = __ldg(&W[(HOFF + k0 + 4 * kc + 1) * NGATE + c0]);
        float w2 = __ldg(&W[(HOFF + k0 + 4 * kc + 2) * NGATE + c0]);
        float w3 = __ldg(&W[(HOFF + k0 + 4 * kc + 3) * NGATE + c0]);
        wr[2 * kc + 0] = f2_to_ull(w0, w1);
        wr[2 * kc + 1] = f2_to_ull(w2, w3);
    }

    // cap-gate contributions (only half 0 applies x-gate terms)
    float capA0 = 0.f, capA1 = 0.f, capA2 = 0.f, capB0 = 0.f, capB1 = 0.f, capB2 = 0.f;
    if (half == 0) {
        capA0 = __ldg(&capd[0 * NGATE + c0]);
        capA1 = __ldg(&capd[1 * NGATE + c0]);
        capA2 = __ldg(&capd[2 * NGATE + c0]);
        capB0 = __ldg(&capd[0 * NGATE + c1]);
        capB1 = __ldg(&capd[1 * NGATE + c1]);
        capB2 = __ldg(&capd[2 * NGATE + c1]);
    }

    // gate-update mapping: thread tid owns (row, unit)
    const int row = tid >> 7;      // 0..3
    const int u   = tid & 127;
    float cst = 0.0f, hh = 0.0f;

    __syncthreads();

    // index + xg pipeline: widx/cidx hold step-t indices; xa*/xb* hold step-t x-gates
    int widx[4], cidx[4];
    float xa0 = 0.f, xa1 = 0.f, xa2 = 0.f, xa3 = 0.f;
    float xb0 = 0.f, xb1 = 0.f, xb2 = 0.f, xb3 = 0.f;
    {
        int t0 = d ? (TSTEPS - 1) : 0;
#pragma unroll
        for (int r = 0; r < 4; r++) {
            widx[r] = __ldg(&words[(b0 + r) * TSTEPS + t0]);
            cidx[r] = __ldg(&caps [(b0 + r) * TSTEPS + t0]);
        }
        if (half == 0) {
            xa0 = __ldg(&tabd[(size_t)widx[0] * NGATE + c0]);
            xa1 = __ldg(&tabd[(size_t)widx[1] * NGATE + c0]);
            xa2 = __ldg(&tabd[(size_t)widx[2] * NGATE + c0]);
            xa3 = __ldg(&tabd[(size_t)widx[3] * NGATE + c0]);
            xb0 = __ldg(&tabd[(size_t)widx[0] * NGATE + c1]);
            xb1 = __ldg(&tabd[(size_t)widx[1] * NGATE + c1]);
            xb2 = __ldg(&tabd[(size_t)widx[2] * NGATE + c1]);
            xb3 = __ldg(&tabd[(size_t)widx[3] * NGATE + c1]);
            xa0 += (cidx[0] == 0) ? capA0 : ((cidx[0] == 1) ? capA1 : capA2);
            xa1 += (cidx[1] == 0) ? capA0 : ((cidx[1] == 1) ? capA1 : capA2);
            xa2 += (cidx[2] == 0) ? capA0 : ((cidx[2] == 1) ? capA1 : capA2);
            xa3 += (cidx[3] == 0) ? capA0 : ((cidx[3] == 1) ? capA1 : capA2);
            xb0 += (cidx[0] == 0) ? capB0 : ((cidx[0] == 1) ? capB1 : capB2);
            xb1 += (cidx[1] == 0) ? capB0 : ((cidx[1] == 1) ? capB1 : capB2);
            xb2 += (cidx[2] == 0) ? capB0 : ((cidx[2] == 1) ? capB1 : capB2);
            xb3 += (cidx[3] == 0) ? capB0 : ((cidx[3] == 1) ? capB1 : capB2);
        }
    }

    for (int t = 0; t < TSTEPS; t++) {
        // prefetch indices for step t+1 (L1-hot broadcast loads)
        int nwidx[4], ncidx[4];
        {
            int tt = d ? (TSTEPS - 2 - t) : (t + 1);
            if (t + 1 >= TSTEPS) tt = 0;   // clamp: values unused
#pragma unroll
            for (int r = 0; r < 4; r++) {
                nwidx[r] = __ldg(&words[(b0 + r) * TSTEPS + tt]);
                ncidx[r] = __ldg(&caps [(b0 + r) * TSTEPS + tt]);
            }
        }

        // recurrent partial GEMM: 2 cols x 4 rows, k in [k0, k0+64), f32x2 k-pairs.
        // Fully unrolled so wr[] stays register-resident.
        unsigned long long A0 = 0ull, A1 = 0ull, A2 = 0ull, A3 = 0ull;   // col c0 (reg w)
        unsigned long long E0 = 0ull, E1 = 0ull, E2 = 0ull, E3 = 0ull;   // col c1 (smem w)
#pragma unroll
        for (int kc = 0; kc < 16; kc++) {
            const int kk = 4 * kc;
            ulonglong2 w1 = *(const ulonglong2*)&wc1[kk];               // LDS.128
            ulonglong2 h0 = *(const ulonglong2*)&h_s[0 * HID + k0 + kk];  // broadcast
            ulonglong2 h1 = *(const ulonglong2*)&h_s[1 * HID + k0 + kk];
            ulonglong2 h2 = *(const ulonglong2*)&h_s[2 * HID + k0 + kk];
            ulonglong2 h3 = *(const ulonglong2*)&h_s[3 * HID + k0 + kk];
            unsigned long long w0x = wr[2 * kc + 0];
            unsigned long long w0y = wr[2 * kc + 1];
            ffma2(A0, h0.x, w0x); ffma2(A0, h0.y, w0y);
            ffma2(A1, h1.x, w0x); ffma2(A1, h1.y, w0y);
            ffma2(A2, h2.x, w0x); ffma2(A2, h2.y, w0y);
            ffma2(A3, h3.x, w0x); ffma2(A3, h3.y, w0y);
            ffma2(E0, h0.x, w1.x); ffma2(E0, h0.y, w1.y);
            ffma2(E1, h1.x, w1.x); ffma2(E1, h1.y, w1.y);
            ffma2(E2, h2.x, w1.x); ffma2(E2, h2.y, w1.y);
            ffma2(E3, h3.x, w1.x); ffma2(E3, h3.y, w1.y);
        }
        {
            float2 f;
            f = ull2f2(A0); gh[0 * GPITCH + c0] = f.x + f.y + xa0;
            f = ull2f2(A1); gh[1 * GPITCH + c0] = f.x + f.y + xa1;
            f = ull2f2(A2); gh[2 * GPITCH + c0] = f.x + f.y + xa2;
            f = ull2f2(A3); gh[3 * GPITCH + c0] = f.x + f.y + xa3;
            f = ull2f2(E0); gh[0 * GPITCH + c1] = f.x + f.y + xb0;
            f = ull2f2(E1); gh[1 * GPITCH + c1] = f.x + f.y + xb1;
            f = ull2f2(E2); gh[2 * GPITCH + c1] = f.x + f.y + xb2;
            f = ull2f2(E3); gh[3 * GPITCH + c1] = f.x + f.y + xb3;
        }

        // issue x-gate gathers for step t+1 NOW (consumed after barrier + next k-loop)
        if (half == 0 && t + 1 < TSTEPS) {
            xa0 = __ldg(&tabd[(size_t)nwidx[0] * NGATE + c0]);
            xa1 = __ldg(&tabd[(size_t)nwidx[1] * NGATE + c0]);
            xa2 = __ldg(&tabd[(size_t)nwidx[2] * NGATE + c0]);
            xa3 = __ldg(&tabd[(size_t)nwidx[3] * NGATE + c0]);
            xb0 = __ldg(&tabd[(size_t)nwidx[0] * NGATE + c1]);
            xb1 = __ldg(&tabd[(size_t)nwidx[1] * NGATE + c1]);
            xb2 = __ldg(&tabd[(size_t)nwidx[2] * NGATE + c1]);
            xb3 = __ldg(&tabd[(size_t)nwidx[3] * NGATE + c1]);
            xa0 += (ncidx[0] == 0) ? capA0 : ((ncidx[0] == 1) ? capA1 : capA2);
            xa1 += (ncidx[1] == 0) ? capA0 : ((ncidx[1] == 1) ? capA1 : capA2);
            xa2 += (ncidx[2] == 0) ? capA0 : ((ncidx[2] == 1) ? capA1 : capA2);
            xa3 += (ncidx[3] == 0) ? capA0 : ((ncidx[3] == 1) ? capA1 : capA2);
            xb0 += (ncidx[0] == 0) ? capB0 : ((ncidx[0] == 1) ? capB1 : capB2);
            xb1 += (ncidx[1] == 0) ? capB0 : ((ncidx[1] == 1) ? capB1 : capB2);
            xb2 += (ncidx[2] == 0) ? capB0 : ((ncidx[2] == 1) ? capB1 : capB2);
            xb3 += (ncidx[3] == 0) ? capB0 : ((ncidx[3] == 1) ? capB1 : capB2);
        }
#pragma unroll
        for (int r = 0; r < 4; r++) { widx[r] = nwidx[r]; cidx[r] = ncidx[r]; }

        __syncthreads();

        // gate update: thread tid owns (row, u); sums the two k-half partials
        {
            float gi = g_s[row * GPITCH + u]           + g_s[4 * GPITCH + row * GPITCH + u];
            float gj = g_s[row * GPITCH + u + HID]     + g_s[4 * GPITCH + row * GPITCH + u + HID];
            float gf = g_s[row * GPITCH + u + 2 * HID] + g_s[4 * GPITCH + row * GPITCH + u + 2 * HID];
            float go = g_s[row * GPITCH + u + 3 * HID] + g_s[4 * GPITCH + row * GPITCH + u + 3 * HID];
            cst = sigf(gf + 1.0f) * cst + sigf(gi) * tanh_fast(gj);
            hh  = sigf(go) * tanh_fast(cst);
            h_s[row * HID + u] = hh;
        }
        __syncthreads();
    }

    g_hfinal[((d * BATCH) + (b0 + row)) * HID + u] = hh;
}

// ---------------- kernel 4: dense head ----------------
__global__ void __launch_bounds__(256) dense_kernel(const float* __restrict__ W1,
                                                    const float* __restrict__ b1,
                                                    const float* __restrict__ W2,
                                                    const float* __restrict__ b2,
                                                    float* __restrict__ out)
{
    __shared__ float red[256];
    __shared__ float d1[DENSE];
    const int b = blockIdx.x, t = threadIdx.x;
    const int j = t & 63, q = t >> 6;
    const float* xin = (q < 2) ? &g_hfinal[b * HID + q * 64]
                               : &g_hfinal[(BATCH + b) * HID + (q - 2) * 64];
    const float* w   = &W1[(q * 64) * DENSE + j];
    float acc = 0.0f;
#pragma unroll 8
    for (int i = 0; i < 64; i++) acc += xin[i] * w[i * DENSE];
    red[t] = acc;
    __syncthreads();
    if (t < DENSE) {
        float a = red[t] + red[t + 64] + red[t + 128] + red[t + 192] + b1[t];
        d1[t] = (a > 0.0f) ? a : (__expf(a) - 1.0f);   // elu
    }
    __syncthreads();
    if (t < NC) {
        float a = b2[t];
#pragma unroll
        for (int k = 0; k < DENSE; k++) a += d1[k] * W2[k * NC + t];
        out[b * NC + t] = 1.0f / (1.0f + __expf(-a));  // sigmoid
    }
}

// ---------------- launch ----------------
extern "C" void kernel_launch(void* const* d_in, const int* in_sizes, int n_in,
                              void* d_out, int out_size)
{
    const int*   words = (const int*)  d_in[0];
    const int*   caps  = (const int*)  d_in[1];
    const float* emb   = (const float*)d_in[2];
    const float* cemb  = (const float*)d_in[3];
    const float* Wfw   = (const float*)d_in[4];
    const float* bfw   = (const float*)d_in[5];
    const float* Wbw   = (const float*)d_in[6];
    const float* bbw   = (const float*)d_in[7];
    const float* W1    = (const float*)d_in[8];
    const float* b1    = (const float*)d_in[9];
    const float* W2    = (const float*)d_in[10];
    const float* b2    = (const float*)d_in[11];
    float* out = (float*)d_out;

    cudaFuncSetAttribute(scan_kernel, cudaFuncAttributeMaxDynamicSharedMemorySize,
                         SCAN_SMEM_BYTES);

    captab_kernel<<<8, 512>>>(cemb, Wfw, bfw, Wbw, bbw);
    tab_kernel<<<dim3((VOCABP + 15) / 16, 2), 512>>>(emb, Wfw, Wbw);
    scan_kernel<<<128, SCAN_T, SCAN_SMEM_BYTES>>>(words, caps, Wfw, Wbw);
    dense_kernel<<<BATCH, 256>>>(W1, b1, W2, b2, out);
}

// round 13
// speedup vs baseline: 1.5986x; 1.1597x over previous
#include <cuda_runtime.h>
#include <cstddef>

#define VOCABP 50001
#define EMB    200
#define HID    128
#define BATCH  256
#define TSTEPS 500
#define NC     6
#define DENSE  64
#define NGATE  512   // 4*HID
#define HOFF   203   // row offset of h-part inside W [331, 512]

#define SCAN_T    512                 // thread = (half = tid>>8, j = tid&255): cols {j, j+256}, k-half
#define SMEM_COLS 256                 // c1 columns (256..511) cached in SMEM, transposed
#define WPITCH    132                 // transposed weight pitch in floats (528B; bank stride 4)
#define GPITCH    512                 // gate staging pitch
// Ws(256*132) + h(4*128) + g(2*4*512) floats = 153,600 B (needs >48KB opt-in)
#define SCAN_SMEM_BYTES ((SMEM_COLS*WPITCH + 4*HID + 2*4*GPITCH) * 4)

// ---------------- scratch (no allocations allowed) ----------------
__device__ float g_tab[2ull * VOCABP * NGATE];    // projected vocab tables, ~205 MB
__device__ float g_captab[2 * 4 * NGATE];         // cap one-hot projection + bias
__device__ float g_hfinal[2 * BATCH * HID];       // final hidden states per direction

__device__ __forceinline__ float sigf(float x) { return 1.0f / (1.0f + __expf(-x)); }
__device__ __forceinline__ float tanh_fast(float x) {
    return 1.0f - 2.0f / (__expf(2.0f * x) + 1.0f);
}

// packed fp32x2 FMA: d.lo += a.lo*b.lo ; d.hi += a.hi*b.hi   (exact fp32 per lane)
__device__ __forceinline__ void ffma2(unsigned long long& d,
                                      unsigned long long a, unsigned long long b) {
    asm("fma.rn.f32x2 %0, %1, %2, %0;" : "+l"(d) : "l"(a), "l"(b));
}
__device__ __forceinline__ float2 ull2f2(unsigned long long v) {
    float2 r; asm("mov.b64 {%0,%1}, %2;" : "=f"(r.x), "=f"(r.y) : "l"(v)); return r;
}
__device__ __forceinline__ unsigned long long fdup(float w) {
    unsigned long long r; asm("mov.b64 %0, {%1,%1};" : "=l"(r) : "f"(w)); return r;
}
__device__ __forceinline__ unsigned long long f2_to_ull(float x, float y) {
    unsigned long long r; asm("mov.b64 %0, {%1,%2};" : "=l"(r) : "f"(x), "f"(y)); return r;
}

// ---------------- kernel 1: Tab[d] = word_emb @ W_d[0:200,:] ----------------
__global__ void __launch_bounds__(512) tab_kernel(const float* __restrict__ emb,
                                                  const float* __restrict__ Wfw,
                                                  const float* __restrict__ Wbw)
{
    __shared__ float es[EMB * 16];   // [k][r] transposed tile, 12.8 KB
    const int d  = blockIdx.y;
    const int v0 = blockIdx.x * 16;
    const float* __restrict__ W = d ? Wbw : Wfw;
    const int tid = threadIdx.x;

    for (int i = tid; i < 16 * EMB; i += 512) {
        int r = i / EMB, k = i % EMB;
        int v = v0 + r;
        es[k * 16 + r] = (v < VOCABP) ? emb[(size_t)v * EMB + k] : 0.0f;
    }
    __syncthreads();

    const int c = tid;   // gate column 0..511
    unsigned long long acc[8];  // 8 packed pairs = 16 rows
#pragma unroll
    for (int p = 0; p < 8; p++) acc[p] = 0ull;

#pragma unroll 4
    for (int k = 0; k < EMB; k++) {
        unsigned long long wd = fdup(__ldg(&W[k * NGATE + c]));
        const ulonglong2* e2 = (const ulonglong2*)&es[k * 16];
        ulonglong2 ea = e2[0], eb = e2[1], ec = e2[2], ed = e2[3];
        ffma2(acc[0], ea.x, wd); ffma2(acc[1], ea.y, wd);
        ffma2(acc[2], eb.x, wd); ffma2(acc[3], eb.y, wd);
        ffma2(acc[4], ec.x, wd); ffma2(acc[5], ec.y, wd);
        ffma2(acc[6], ed.x, wd); ffma2(acc[7], ed.y, wd);
    }

    float* out = &g_tab[((size_t)d * VOCABP + v0) * NGATE + c];
#pragma unroll
    for (int p = 0; p < 8; p++) {
        float2 f = ull2f2(acc[p]);
        if (v0 + 2 * p     < VOCABP) out[(size_t)(2 * p)     * NGATE] = f.x;
        if (v0 + 2 * p + 1 < VOCABP) out[(size_t)(2 * p + 1) * NGATE] = f.y;
    }
}

// ---------------- kernel 2: cap table (+ bias folded in) ----------------
__global__ void captab_kernel(const float* __restrict__ cemb,
                              const float* __restrict__ Wfw, const float* __restrict__ bfw,
                              const float* __restrict__ Wbw, const float* __restrict__ bbw)
{
    int idx = blockIdx.x * blockDim.x + threadIdx.x;
    if (idx >= 2 * 4 * NGATE) return;
    int d  = idx / (4 * NGATE);
    int ci = (idx / NGATE) & 3;
    int c  = idx % NGATE;
    const float* W = d ? Wbw : Wfw;
    const float* b = d ? bbw : bfw;
    float v = b[c];
#pragma unroll
    for (int j = 0; j < 3; j++) v += cemb[ci * 3 + j] * W[(EMB + j) * NGATE + c];
    g_captab[idx] = v;
}

// ---------------- kernel 3: the recurrent scan ----------------
// grid = 128 CTAs: blockIdx.x>>6 = direction, (blockIdx.x&63)*4 = first batch row.
// Producer role: thread (half = tid>>8, j = tid&255) computes partial gates for
//   columns {j, j+256} x 4 rows over k in [half*64, half*64+64).
//   c0 weights in 32 packed f32x2 registers; c1 weights from SMEM.
// Consumer role: thread (row = tid>>7, u = tid&127) loads its own x-gate values
//   (tab + cap, 8 coalesced LDG issued at step start, consumed in the epilogue)
//   and performs the gate update. No xg state in the k-loop -> low reg pressure.
__global__ void __launch_bounds__(SCAN_T, 1) scan_kernel(const int* __restrict__ words,
                                                         const int* __restrict__ caps,
                                                         const float* __restrict__ Wfw,
                                                         const float* __restrict__ Wbw)
{
    extern __shared__ float sm[];
    float* Ws  = sm;                        // [SMEM_COLS][WPITCH] transposed c1 weights
    float* h_s = Ws + SMEM_COLS * WPITCH;   // [4][HID]
    float* g_s = h_s + 4 * HID;             // [2 halves][4][GPITCH]

    const int tid = threadIdx.x;
    const int d   = blockIdx.x >> 6;
    const int b0  = (blockIdx.x & 63) * 4;
    const float* __restrict__ W = d ? Wbw : Wfw;

    // stage c1 columns [256, 512) transposed: Ws[c-256][k]  (one-time cost)
    for (int i = tid; i < HID * SMEM_COLS; i += SCAN_T) {
        int k = i / SMEM_COLS, c = i % SMEM_COLS;   // coalesced global read
        Ws[c * WPITCH + k] = W[(HOFF + k) * NGATE + 256 + c];
    }
    h_s[tid] = 0.0f;   // 512 = 4*HID exactly

    const int half = tid >> 8;          // k-half: 0 -> [0,64), 1 -> [64,128)
    const int j    = tid & 255;
    const int c0   = j;                 // register-resident weights
    const int k0   = half * 64;
    const float* __restrict__ tabd = &g_tab[(size_t)d * VOCABP * NGATE];
    const float* __restrict__ capd = &g_captab[d * 4 * NGATE];
    const float* __restrict__ wc1  = &Ws[j * WPITCH + k0];
    float* gh = g_s + half * 4 * GPITCH;   // this half's staging buffer

    // c0 weights: 64 fp32 -> 32 packed f32x2 registers (coalesced one-time load)
    unsigned long long wr[32];
#pragma unroll
    for (int kc = 0; kc < 16; kc++) {
        float w0 = __ldg(&W[(HOFF + k0 + 4 * kc + 0) * NGATE + c0]);
        float w1 = __ldg(&W[(HOFF + k0 + 4 * kc + 1) * NGATE + c0]);
        float w2 = __ldg(&W[(HOFF + k0 + 4 * kc + 2) * NGATE + c0]);
        float w3 = __ldg(&W[(HOFF + k0 + 4 * kc + 3) * NGATE + c0]);
        wr[2 * kc + 0] = f2_to_ull(w0, w1);
        wr[2 * kc + 1] = f2_to_ull(w2, w3);
    }

    // consumer-role mapping: thread tid owns (row, unit)
    const int row = tid >> 7;      // 0..3
    const int u   = tid & 127;
    const int* __restrict__ wrow = &words[(b0 + row) * TSTEPS];
    const int* __restrict__ crow = &caps [(b0 + row) * TSTEPS];
    float cst = 0.0f, hh = 0.0f;

    __syncthreads();

    // prologue: indices for step 0
    int wv, cv;
    {
        int t0 = d ? (TSTEPS - 1) : 0;
        wv = __ldg(&wrow[t0]);
        cv = __ldg(&crow[t0]);
    }

    for (int t = 0; t < TSTEPS; t++) {
        // ---- step start: issue this step's x-gate loads (consumed in epilogue) ----
        const float* tr = &tabd[(size_t)wv * NGATE];
        const float* cr = &capd[(size_t)cv * NGATE];
        float xi = __ldg(&tr[u]);
        float xj = __ldg(&tr[u + 128]);
        float xf = __ldg(&tr[u + 256]);
        float xo = __ldg(&tr[u + 384]);
        float ki = __ldg(&cr[u]);
        float kj = __ldg(&cr[u + 128]);
        float kf = __ldg(&cr[u + 256]);
        float ko = __ldg(&cr[u + 384]);

        // prefetch next step's indices (L1-hot)
        {
            int tt = d ? (TSTEPS - 2 - t) : (t + 1);
            if (t + 1 >= TSTEPS) tt = 0;   // clamp: values unused
            wv = __ldg(&wrow[tt]);
            cv = __ldg(&crow[tt]);
        }

        // ---- producer: partial GEMM, 2 cols x 4 rows, k in [k0, k0+64) ----
        unsigned long long A0 = 0ull, A1 = 0ull, A2 = 0ull, A3 = 0ull;   // col c0 (reg w)
        unsigned long long E0 = 0ull, E1 = 0ull, E2 = 0ull, E3 = 0ull;   // col c1 (smem w)
#pragma unroll
        for (int kc = 0; kc < 16; kc++) {
            const int kk = 4 * kc;
            ulonglong2 w1 = *(const ulonglong2*)&wc1[kk];                 // LDS.128
            ulonglong2 h0 = *(const ulonglong2*)&h_s[0 * HID + k0 + kk];  // broadcast
            ulonglong2 h1 = *(const ulonglong2*)&h_s[1 * HID + k0 + kk];
            ulonglong2 h2 = *(const ulonglong2*)&h_s[2 * HID + k0 + kk];
            ulonglong2 h3 = *(const ulonglong2*)&h_s[3 * HID + k0 + kk];
            unsigned long long w0x = wr[2 * kc + 0];
            unsigned long long w0y = wr[2 * kc + 1];
            ffma2(A0, h0.x, w0x); ffma2(A0, h0.y, w0y);
            ffma2(A1, h1.x, w0x); ffma2(A1, h1.y, w0y);
            ffma2(A2, h2.x, w0x); ffma2(A2, h2.y, w0y);
            ffma2(A3, h3.x, w0x); ffma2(A3, h3.y, w0y);
            ffma2(E0, h0.x, w1.x); ffma2(E0, h0.y, w1.y);
            ffma2(E1, h1.x, w1.x); ffma2(E1, h1.y, w1.y);
            ffma2(E2, h2.x, w1.x); ffma2(E2, h2.y, w1.y);
            ffma2(E3, h3.x, w1.x); ffma2(E3, h3.y, w1.y);
        }
        {
            float2 f;
            f = ull2f2(A0); gh[0 * GPITCH + c0]       = f.x + f.y;
            f = ull2f2(A1); gh[1 * GPITCH + c0]       = f.x + f.y;
            f = ull2f2(A2); gh[2 * GPITCH + c0]       = f.x + f.y;
            f = ull2f2(A3); gh[3 * GPITCH + c0]       = f.x + f.y;
            f = ull2f2(E0); gh[0 * GPITCH + c0 + 256] = f.x + f.y;
            f = ull2f2(E1); gh[1 * GPITCH + c0 + 256] = f.x + f.y;
            f = ull2f2(E2); gh[2 * GPITCH + c0 + 256] = f.x + f.y;
            f = ull2f2(E3); gh[3 * GPITCH + c0 + 256] = f.x + f.y;
        }
        __syncthreads();

        // ---- consumer: gate update for (row, u); sums halves + x-gates ----
        {
            float gi = g_s[row * GPITCH + u]           + g_s[4 * GPITCH + row * GPITCH + u]           + xi + ki;
            float gj = g_s[row * GPITCH + u + HID]     + g_s[4 * GPITCH + row * GPITCH + u + HID]     + xj + kj;
            float gf = g_s[row * GPITCH + u + 2 * HID] + g_s[4 * GPITCH + row * GPITCH + u + 2 * HID] + xf + kf;
            float go = g_s[row * GPITCH + u + 3 * HID] + g_s[4 * GPITCH + row * GPITCH + u + 3 * HID] + xo + ko;
            cst = sigf(gf + 1.0f) * cst + sigf(gi) * tanh_fast(gj);
            hh  = sigf(go) * tanh_fast(cst);
            h_s[row * HID + u] = hh;
        }
        __syncthreads();
    }

    g_hfinal[((d * BATCH) + (b0 + row)) * HID + u] = hh;
}

// ---------------- kernel 4: dense head ----------------
__global__ void __launch_bounds__(256) dense_kernel(const float* __restrict__ W1,
                                                    const float* __restrict__ b1,
                                                    const float* __restrict__ W2,
                                                    const float* __restrict__ b2,
                                                    float* __restrict__ out)
{
    __shared__ float red[256];
    __shared__ float d1[DENSE];
    const int b = blockIdx.x, t = threadIdx.x;
    const int j = t & 63, q = t >> 6;
    const float* xin = (q < 2) ? &g_hfinal[b * HID + q * 64]
                               : &g_hfinal[(BATCH + b) * HID + (q - 2) * 64];
    const float* w   = &W1[(q * 64) * DENSE + j];
    float acc = 0.0f;
#pragma unroll 8
    for (int i = 0; i < 64; i++) acc += xin[i] * w[i * DENSE];
    red[t] = acc;
    __syncthreads();
    if (t < DENSE) {
        float a = red[t] + red[t + 64] + red[t + 128] + red[t + 192] + b1[t];
        d1[t] = (a > 0.0f) ? a : (__expf(a) - 1.0f);   // elu
    }
    __syncthreads();
    if (t < NC) {
        float a = b2[t];
#pragma unroll
        for (int k = 0; k < DENSE; k++) a += d1[k] * W2[k * NC + t];
        out[b * NC + t] = 1.0f / (1.0f + __expf(-a));  // sigmoid
    }
}

// ---------------- launch ----------------
extern "C" void kernel_launch(void* const* d_in, const int* in_sizes, int n_in,
                              void* d_out, int out_size)
{
    const int*   words = (const int*)  d_in[0];
    const int*   caps  = (const int*)  d_in[1];
    const float* emb   = (const float*)d_in[2];
    const float* cemb  = (const float*)d_in[3];
    const float* Wfw   = (const float*)d_in[4];
    const float* bfw   = (const float*)d_in[5];
    const float* Wbw   = (const float*)d_in[6];
    const float* bbw   = (const float*)d_in[7];
    const float* W1    = (const float*)d_in[8];
    const float* b1    = (const float*)d_in[9];
    const float* W2    = (const float*)d_in[10];
    const float* b2    = (const float*)d_in[11];
    float* out = (float*)d_out;

    cudaFuncSetAttribute(scan_kernel, cudaFuncAttributeMaxDynamicSharedMemorySize,
                         SCAN_SMEM_BYTES);

    captab_kernel<<<8, 512>>>(cemb, Wfw, bfw, Wbw, bbw);
    tab_kernel<<<dim3((VOCABP + 15) / 16, 2), 512>>>(emb, Wfw, Wbw);
    scan_kernel<<<128, SCAN_T, SCAN_SMEM_BYTES>>>(words, caps, Wfw, Wbw);
    dense_kernel<<<BATCH, 256>>>(W1, b1, W2, b2, out);
}